// round 13
// baseline (speedup 1.0000x reference)
#include <cuda_runtime.h>
#include <cuda_fp16.h>
#include <cstdint>
#include <math.h>

// ---------------------------------------------------------------------------
// Problem constants
// ---------------------------------------------------------------------------
#define BATCH 16
#define CIN   256
#define COUT  256
#define HH    56
#define WW    56
#define HWSZ  3136
#define NEXP  8
#define KTOT  2304          // 9 * 256, reordered k' = kpos*256 + ci
#define PROW  58            // padded row width
#define PPAD  64            // leading guard rows in pimg
#define PTOT  3712          // guard + 58*58 + tail guard
#define NCH   36            // K chunks of 64
#define NT    27            // N tiles of 128 over 3364 padded px

// ---------------------------------------------------------------------------
// Global scratch (no cudaMalloc allowed; __device__ globals are zero-init)
// ---------------------------------------------------------------------------
__device__ float g_pooled[BATCH * CIN];
__device__ float g_r[BATCH * NEXP];
__device__ __half g_pimg[(size_t)BATCH * PTOT * CIN];
__device__ __half g_cw[(size_t)BATCH * COUT * KTOT];

// ---------------------------------------------------------------------------
// Helpers (portable PTX only: sm_80-class features, safe at compute_103)
// ---------------------------------------------------------------------------
#define SWZ(o) ((o) ^ (((o) >> 3) & 0x70))

static __device__ __forceinline__ uint32_t smem_u32(const void* p) {
    uint32_t a;
    asm("{ .reg .u64 t; cvta.to.shared.u64 t, %1; cvt.u32.u64 %0, t; }"
        : "=r"(a) : "l"(p));
    return a;
}

static __device__ __forceinline__ void cp16(uint32_t dst, const void* src) {
    size_t g = __cvta_generic_to_global(src);
    asm volatile("cp.async.cg.shared.global [%0], [%1], 16;"
                 :: "r"(dst), "l"(g) : "memory");
}
#define CP_COMMIT() asm volatile("cp.async.commit_group;" ::: "memory")
#define CP_WAIT0()  asm volatile("cp.async.wait_group 0;" ::: "memory")

static __device__ __forceinline__ void ldmx4(uint32_t* r, uint32_t addr) {
    asm volatile("ldmatrix.sync.aligned.m8n8.x4.shared.b16 {%0,%1,%2,%3}, [%4];"
                 : "=r"(r[0]), "=r"(r[1]), "=r"(r[2]), "=r"(r[3]) : "r"(addr));
}

static __device__ __forceinline__ void mma16816(float* d, const uint32_t* a,
                                                uint32_t b0, uint32_t b1) {
    asm volatile(
        "mma.sync.aligned.m16n8k16.row.col.f32.f16.f16.f32 "
        "{%0,%1,%2,%3}, {%4,%5,%6,%7}, {%8,%9}, {%0,%1,%2,%3};"
        : "+f"(d[0]), "+f"(d[1]), "+f"(d[2]), "+f"(d[3])
        : "r"(a[0]), "r"(a[1]), "r"(a[2]), "r"(a[3]), "r"(b0), "r"(b1));
}

// ---------------------------------------------------------------------------
// Kernel 1: global average pool (float4 vectorized)
// ---------------------------------------------------------------------------
__global__ void pool_kernel(const float* __restrict__ x) {
    int bc = blockIdx.x;
    const float4* p = (const float4*)(x + (size_t)bc * HWSZ);
    float s = 0.f;
    for (int i = threadIdx.x; i < HWSZ / 4; i += 128) {
        float4 v = p[i];
        s += (v.x + v.y) + (v.z + v.w);
    }
    #pragma unroll
    for (int o = 16; o > 0; o >>= 1) s += __shfl_down_sync(0xffffffffu, s, o);
    __shared__ float red[4];
    if ((threadIdx.x & 31) == 0) red[threadIdx.x >> 5] = s;
    __syncthreads();
    if (threadIdx.x == 0)
        g_pooled[bc] = (red[0] + red[1] + red[2] + red[3]) * (1.0f / HWSZ);
}

// ---------------------------------------------------------------------------
// Kernel 2: routing (float4 dot products)
// ---------------------------------------------------------------------------
__global__ void route_kernel(const float* __restrict__ rw,
                             const float* __restrict__ rb) {
    int t = threadIdx.x;
    int b = t >> 3, e = t & 7;
    const float4* p = (const float4*)(g_pooled + b * CIN);
    const float4* w = (const float4*)(rw + e * CIN);
    float a = rb[e];
    #pragma unroll 8
    for (int c = 0; c < CIN / 4; c++) {
        float4 pv = p[c], wv = w[c];
        a += pv.x * wv.x + pv.y * wv.y + pv.z * wv.z + pv.w * wv.w;
    }
    g_r[t] = 1.0f / (1.0f + __expf(-a));
}

// ---------------------------------------------------------------------------
// Kernel 3: combined weights, K-reordered (k' = kpos*256 + ci), fp16.
// ---------------------------------------------------------------------------
__global__ void combine_kernel(const float* __restrict__ kw) {
    __shared__ float rs[BATCH * NEXP];
    if (threadIdx.x < BATCH * NEXP) rs[threadIdx.x] = g_r[threadIdx.x];
    __syncthreads();
    int oc = blockIdx.x, ci = threadIdx.x;
    float wv[NEXP][9];
    #pragma unroll
    for (int e = 0; e < NEXP; e++) {
        const float* p = kw + ((size_t)(e * COUT + oc) * CIN + ci) * 9;
        #pragma unroll
        for (int j = 0; j < 9; j++) wv[e][j] = p[j];
    }
    for (int b = 0; b < BATCH; b++) {
        float a[9];
        #pragma unroll
        for (int j = 0; j < 9; j++) a[j] = 0.f;
        #pragma unroll
        for (int e = 0; e < NEXP; e++) {
            float r = rs[b * NEXP + e];
            #pragma unroll
            for (int j = 0; j < 9; j++) a[j] += r * wv[e][j];
        }
        size_t base = (size_t)(b * COUT + oc) * KTOT;
        #pragma unroll
        for (int j = 0; j < 9; j++)
            g_cw[base + j * 256 + ci] = __float2half_rn(a[j]);
    }
}

// ---------------------------------------------------------------------------
// Kernel 4: padded + transposed image  pimg[b][pos][ci] (fp16)
// pos = PPAD + (r+1)*58 + (w+1); zeros elsewhere.
// Now 128 ci per block (32 in-flight loads/thread for latency hiding).
// grid = (58 pos-tiles of 64, 2 ci-tiles of 128, 16 b), block 256
// ---------------------------------------------------------------------------
__global__ void prep_kernel(const float* __restrict__ x) {
    __shared__ float tile[128][65];
    __shared__ int s_off[64];                 // x-plane offset or -1
    int b = blockIdx.z, ciB = blockIdx.y * 128, posB = blockIdx.x * 64;
    int tid = threadIdx.x;
    if (tid < 64) {
        int p = posB + tid - PPAD;
        int off = -1;
        if (p >= 0) {
            int r = p / PROW - 1, w = p % PROW - 1;
            if (r >= 0 && r < HH && w >= 0 && w < WW) off = r * WW + w;
        }
        s_off[tid] = off;
    }
    __syncthreads();
    #pragma unroll 8
    for (int i = tid; i < 128 * 64; i += 256) {
        int ci_l = i >> 6, pos_l = i & 63;
        int off = s_off[pos_l];
        tile[ci_l][pos_l] = (off >= 0)
            ? x[((size_t)(b * CIN + ciB + ci_l)) * HWSZ + off] : 0.f;
    }
    __syncthreads();
    // half2 writes: 64 pos x 64 ci-pairs
    #pragma unroll 4
    for (int i = tid; i < 64 * 64; i += 256) {
        int pos_l = i >> 6, cp = i & 63;
        __half2 v = __floats2half2_rn(tile[cp * 2][pos_l], tile[cp * 2 + 1][pos_l]);
        *(__half2*)(g_pimg + ((size_t)b * PTOT + posB + pos_l) * CIN + ciB + cp * 2) = v;
    }
}

// ---------------------------------------------------------------------------
// Kernel 5: fp16 mma.sync implicit-GEMM conv + BN + SiLU
// grid = (27 ntiles, 16 b), block 512 (16 warps, 4x4), 192KB dyn smem
// Tile: M256 x N128, BK=64. Warp tile: 64x32.
// B staged ONCE as a 256-row pixel window (shifted views = all 9 kpos tiles).
// A double-buffered; ONE sync per chunk: {wait; sync; stage-next; compute}.
// ---------------------------------------------------------------------------
#define ASTG 32768                 // one A stage (256 rows x 128B)
#define BWIN_OFF (2 * ASTG)        // B window offset
#define SMEM_DYN (2 * ASTG + 131072)

extern __shared__ char smem_raw[];

__global__ __launch_bounds__(512, 1)
void conv_hmma_kernel(const float* __restrict__ bn_gamma,
                      const float* __restrict__ bn_beta,
                      const float* __restrict__ bn_mean,
                      const float* __restrict__ bn_var,
                      float* __restrict__ out) {
    const int tid  = threadIdx.x;
    const int lane = tid & 31;
    const int wid  = tid >> 5;
    const int wm   = wid & 3;          // warp row (0..3) -> 64 oc
    const int wn   = wid >> 2;         // warp col (0..3) -> 32 px
    const int p0   = blockIdx.x * 128;
    const int b    = blockIdx.y;

    const uint32_t sb = smem_u32(smem_raw);
    const uint32_t bw = sb + BWIN_OFF;

    // ---- B window staging: rows p0-59 .. p0+196 (256 rows x 512B) ----
    // store 16B chunk c of row r at column (c ^ (r&7))
    {
        const __half* gp = g_pimg + ((size_t)b * PTOT + PPAD + p0 - 59) * CIN;
        #pragma unroll
        for (int i = 0; i < 16; i++) {
            int idx = i * 512 + tid;
            int r = idx >> 5, c = idx & 31;
            cp16(bw + r * 512 + (((uint32_t)(c ^ (r & 7))) << 4),
                 gp + (size_t)r * CIN + c * 8);
        }
        CP_COMMIT();
    }

    // ---- A staging: 256 rows x 64 ci (128B rows, SW128 swizzle) ----
    const int srow = tid >> 1;               // 0..255
    const int scol = (tid & 1) * 4;          // 16B seg base 0 or 4
    const __half* cwrow = g_cw + (size_t)(b * COUT + srow) * KTOT;

    auto stageA = [&](int it, uint32_t stb) {
        const __half* ga = cwrow + it * 64 + scol * 8;
        uint32_t so = srow * 128 + scol * 16;
        #pragma unroll
        for (int i = 0; i < 4; i++)
            cp16(stb + SWZ(so + i * 16), ga + i * 8);
        CP_COMMIT();
    };

    float d[4][4][4];
    #pragma unroll
    for (int im = 0; im < 4; im++)
        #pragma unroll
        for (int in = 0; in < 4; in++)
            #pragma unroll
            for (int e = 0; e < 4; e++) d[im][in][e] = 0.f;

    // per-lane ldmatrix address pieces
    const int a_row = lane & 15;
    const int a_kh  = (lane >> 4) * 8;
    const int b_mi  = lane >> 3;                         // matrix 0..3
    const int b_row = ((b_mi >> 1) << 3) + (lane & 7);   // n within 16
    const int b_ck  = b_mi & 1;                          // k-half chunk

    stageA(0, sb);

    for (int it = 0; it < NCH; it++) {
        CP_WAIT0();                    // retire A(it) (+Bwin at it=0)
        __syncthreads();               // also separates reads of buf (it+1)&1
        if (it + 1 < NCH) stageA(it + 1, sb + ((it + 1) & 1) * ASTG);

        uint32_t as = sb + (it & 1) * ASTG;
        const int kpos = it >> 2;
        const int cchunk = (it & 3) * 8;     // 16B-chunk base of ci block
        const int woff = 59 + (kpos / 3) * PROW + (kpos % 3) - (PROW + 1);

        #pragma unroll
        for (int kk = 0; kk < 4; kk++) {
            uint32_t a[4][4];
            #pragma unroll
            for (int im = 0; im < 4; im++) {
                uint32_t byte = (wm * 64 + im * 16 + a_row) * 128 +
                                (kk * 16 + a_kh) * 2;
                ldmx4(a[im], as + SWZ(byte));
            }
            uint32_t bf[2][4];
            #pragma unroll
            for (int j = 0; j < 2; j++) {
                int wrow = woff + wn * 32 + j * 16 + b_row;
                int ck   = cchunk + kk * 2 + b_ck;
                ldmx4(bf[j], bw + wrow * 512 +
                             (((uint32_t)(ck ^ (wrow & 7))) << 4));
            }
            #pragma unroll
            for (int im = 0; im < 4; im++)
                #pragma unroll
                for (int in = 0; in < 4; in++)
                    mma16816(d[im][in], a[im],
                             bf[in >> 1][(in & 1) * 2],
                             bf[in >> 1][(in & 1) * 2 + 1]);
        }
    }

    // ---- epilogue: BN + SiLU + masked store ----
    const int t4 = lane >> 2, tp = lane & 3;
    #pragma unroll
    for (int im = 0; im < 4; im++) {
        int mloc = wm * 64 + im * 16 + t4;
        #pragma unroll
        for (int h = 0; h < 2; h++) {
            int oc = mloc + h * 8;
            float inv = bn_gamma[oc] * rsqrtf(bn_var[oc] + 1e-5f);
            float bia = bn_beta[oc] - bn_mean[oc] * inv;
            float* ob = out + (size_t)(b * COUT + oc) * HWSZ;
            #pragma unroll
            for (int in = 0; in < 4; in++) {
                int pbase = p0 + wn * 32 + in * 8 + tp * 2;
                #pragma unroll
                for (int e = 0; e < 2; e++) {
                    int p = pbase + e;
                    int rr = p / PROW - 1, ww = p % PROW - 1;
                    if (rr >= 0 && rr < HH && ww >= 0 && ww < WW) {
                        float z = d[im][in][h * 2 + e] * inv + bia;
                        ob[rr * WW + ww] = z / (1.f + __expf(-z));
                    }
                }
            }
        }
    }
}

// ---------------------------------------------------------------------------
extern "C" void kernel_launch(void* const* d_in, const int* in_sizes, int n_in,
                              void* d_out, int out_size) {
    const float* x         = (const float*)d_in[0];
    const float* routing_w = (const float*)d_in[1];
    const float* routing_b = (const float*)d_in[2];
    const float* kernel_w  = (const float*)d_in[3];
    const float* bn_gamma  = (const float*)d_in[4];
    const float* bn_beta   = (const float*)d_in[5];
    const float* bn_mean   = (const float*)d_in[6];
    const float* bn_var    = (const float*)d_in[7];
    float* out = (float*)d_out;

    cudaFuncSetAttribute(conv_hmma_kernel,
                         cudaFuncAttributeMaxDynamicSharedMemorySize, SMEM_DYN);

    pool_kernel<<<BATCH * CIN, 128>>>(x);
    route_kernel<<<1, 128>>>(routing_w, routing_b);
    combine_kernel<<<COUT, 256>>>(kernel_w);
    prep_kernel<<<dim3(PTOT / 64, CIN / 128, BATCH), 256>>>(x);

    dim3 grid(NT, BATCH);
    conv_hmma_kernel<<<grid, 512, SMEM_DYN>>>(bn_gamma, bn_beta, bn_mean,
                                              bn_var, out);
}

// round 15
// speedup vs baseline: 1.0741x; 1.0741x over previous
#include <cuda_runtime.h>
#include <cuda_fp16.h>
#include <cstdint>
#include <math.h>

// ---------------------------------------------------------------------------
// Problem constants
// ---------------------------------------------------------------------------
#define BATCH 16
#define CIN   256
#define COUT  256
#define HH    56
#define WW    56
#define HWSZ  3136
#define NEXP  8
#define KTOT  2304          // 9 * 256, reordered k' = kpos*256 + ci
#define PROW  58            // padded row width
#define PPAD  64            // leading guard rows in pimg
#define PTOT  3712          // guard + 58*58 + tail guard
#define NCH   36            // K chunks of 64
#define NT    27            // N tiles of 128 over 3364 padded px

// ---------------------------------------------------------------------------
// Global scratch (no cudaMalloc allowed; __device__ globals are zero-init)
// ---------------------------------------------------------------------------
__device__ float g_pooled[BATCH * CIN];
__device__ float g_r[BATCH * NEXP];
__device__ __half g_pimg[(size_t)BATCH * PTOT * CIN];
__device__ __half g_cw[(size_t)BATCH * COUT * KTOT];

// ---------------------------------------------------------------------------
// Helpers (portable PTX only: sm_80-class features, safe at compute_103)
// ---------------------------------------------------------------------------
#define SWZ(o) ((o) ^ (((o) >> 3) & 0x70))

static __device__ __forceinline__ uint32_t smem_u32(const void* p) {
    uint32_t a;
    asm("{ .reg .u64 t; cvta.to.shared.u64 t, %1; cvt.u32.u64 %0, t; }"
        : "=r"(a) : "l"(p));
    return a;
}

static __device__ __forceinline__ void cp16(uint32_t dst, const void* src) {
    size_t g = __cvta_generic_to_global(src);
    asm volatile("cp.async.cg.shared.global [%0], [%1], 16;"
                 :: "r"(dst), "l"(g) : "memory");
}
#define CP_COMMIT() asm volatile("cp.async.commit_group;" ::: "memory")
#define CP_WAIT0()  asm volatile("cp.async.wait_group 0;" ::: "memory")

static __device__ __forceinline__ void ldmx4(uint32_t* r, uint32_t addr) {
    asm volatile("ldmatrix.sync.aligned.m8n8.x4.shared.b16 {%0,%1,%2,%3}, [%4];"
                 : "=r"(r[0]), "=r"(r[1]), "=r"(r[2]), "=r"(r[3]) : "r"(addr));
}

static __device__ __forceinline__ void mma16816(float* d, const uint32_t* a,
                                                uint32_t b0, uint32_t b1) {
    asm volatile(
        "mma.sync.aligned.m16n8k16.row.col.f32.f16.f16.f32 "
        "{%0,%1,%2,%3}, {%4,%5,%6,%7}, {%8,%9}, {%0,%1,%2,%3};"
        : "+f"(d[0]), "+f"(d[1]), "+f"(d[2]), "+f"(d[3])
        : "r"(a[0]), "r"(a[1]), "r"(a[2]), "r"(a[3]), "r"(b0), "r"(b1));
}

// ---------------------------------------------------------------------------
// Kernel 1: global average pool (float4 vectorized)
// ---------------------------------------------------------------------------
__global__ void pool_kernel(const float* __restrict__ x) {
    int bc = blockIdx.x;
    const float4* p = (const float4*)(x + (size_t)bc * HWSZ);
    float s = 0.f;
    for (int i = threadIdx.x; i < HWSZ / 4; i += 128) {
        float4 v = p[i];
        s += (v.x + v.y) + (v.z + v.w);
    }
    #pragma unroll
    for (int o = 16; o > 0; o >>= 1) s += __shfl_down_sync(0xffffffffu, s, o);
    __shared__ float red[4];
    if ((threadIdx.x & 31) == 0) red[threadIdx.x >> 5] = s;
    __syncthreads();
    if (threadIdx.x == 0)
        g_pooled[bc] = (red[0] + red[1] + red[2] + red[3]) * (1.0f / HWSZ);
}

// ---------------------------------------------------------------------------
// Kernel 2: routing (float4 dot products)
// ---------------------------------------------------------------------------
__global__ void route_kernel(const float* __restrict__ rw,
                             const float* __restrict__ rb) {
    int t = threadIdx.x;
    int b = t >> 3, e = t & 7;
    const float4* p = (const float4*)(g_pooled + b * CIN);
    const float4* w = (const float4*)(rw + e * CIN);
    float a = rb[e];
    #pragma unroll 8
    for (int c = 0; c < CIN / 4; c++) {
        float4 pv = p[c], wv = w[c];
        a += pv.x * wv.x + pv.y * wv.y + pv.z * wv.z + pv.w * wv.w;
    }
    g_r[t] = 1.0f / (1.0f + __expf(-a));
}

// ---------------------------------------------------------------------------
// Kernel 3: combined weights, K-reordered (k' = kpos*256 + ci), fp16.
// ---------------------------------------------------------------------------
__global__ void combine_kernel(const float* __restrict__ kw) {
    __shared__ float rs[BATCH * NEXP];
    if (threadIdx.x < BATCH * NEXP) rs[threadIdx.x] = g_r[threadIdx.x];
    __syncthreads();
    int oc = blockIdx.x, ci = threadIdx.x;
    float wv[NEXP][9];
    #pragma unroll
    for (int e = 0; e < NEXP; e++) {
        const float* p = kw + ((size_t)(e * COUT + oc) * CIN + ci) * 9;
        #pragma unroll
        for (int j = 0; j < 9; j++) wv[e][j] = p[j];
    }
    for (int b = 0; b < BATCH; b++) {
        float a[9];
        #pragma unroll
        for (int j = 0; j < 9; j++) a[j] = 0.f;
        #pragma unroll
        for (int e = 0; e < NEXP; e++) {
            float r = rs[b * NEXP + e];
            #pragma unroll
            for (int j = 0; j < 9; j++) a[j] += r * wv[e][j];
        }
        size_t base = (size_t)(b * COUT + oc) * KTOT;
        #pragma unroll
        for (int j = 0; j < 9; j++)
            g_cw[base + j * 256 + ci] = __float2half_rn(a[j]);
    }
}

// ---------------------------------------------------------------------------
// Kernel 4: padded + transposed image  pimg[b][pos][ci] (fp16)
// pos = PPAD + (r+1)*58 + (w+1); zeros elsewhere.
// 64 pos x 64 ci per block (17KB smem, occ ~90%); register-batched loads
// (16 independent LDGs in flight per thread) then store phase.
// grid = (58 pos-tiles of 64, 4 ci-tiles of 64, 16 b), block 256
// ---------------------------------------------------------------------------
__global__ void prep_kernel(const float* __restrict__ x) {
    __shared__ float tile[64][65];
    __shared__ int s_off[64];                 // x-plane offset or -1
    int b = blockIdx.z, ciB = blockIdx.y * 64, posB = blockIdx.x * 64;
    int tid = threadIdx.x;
    if (tid < 64) {
        int p = posB + tid - PPAD;
        int off = -1;
        if (p >= 0) {
            int r = p / PROW - 1, w = p % PROW - 1;
            if (r >= 0 && r < HH && w >= 0 && w < WW) off = r * WW + w;
        }
        s_off[tid] = off;
    }
    __syncthreads();
    // load phase: all 16 gathers issued back-to-back (registers), then stores
    {
        float v[16];
        #pragma unroll
        for (int k = 0; k < 16; k++) {
            int i = tid + k * 256;
            int ci_l = i >> 6, pos_l = i & 63;
            int off = s_off[pos_l];
            v[k] = (off >= 0)
                ? __ldg(x + ((size_t)(b * CIN + ciB + ci_l)) * HWSZ + off) : 0.f;
        }
        #pragma unroll
        for (int k = 0; k < 16; k++) {
            int i = tid + k * 256;
            tile[i >> 6][i & 63] = v[k];
        }
    }
    __syncthreads();
    // half2 writes: 64 pos x 32 ci-pairs
    #pragma unroll
    for (int k = 0; k < 8; k++) {
        int i = tid + k * 256;
        int pos_l = i >> 5, cp = i & 31;
        __half2 v = __floats2half2_rn(tile[cp * 2][pos_l], tile[cp * 2 + 1][pos_l]);
        *(__half2*)(g_pimg + ((size_t)b * PTOT + posB + pos_l) * CIN + ciB + cp * 2) = v;
    }
}

// ---------------------------------------------------------------------------
// Kernel 5: fp16 mma.sync implicit-GEMM conv + BN + SiLU
// grid = (27 ntiles, 16 b), block 512 (16 warps, 4x4), 192KB dyn smem
// Tile: M256 x N128, BK=64. Warp tile: 64x32.
// B staged ONCE as a 256-row pixel window (shifted views = all 9 kpos tiles).
// A double-buffered; ONE sync per chunk: {wait; sync; stage-next; compute}.
// ---------------------------------------------------------------------------
#define ASTG 32768                 // one A stage (256 rows x 128B)
#define BWIN_OFF (2 * ASTG)        // B window offset
#define SMEM_DYN (2 * ASTG + 131072)

extern __shared__ char smem_raw[];

__global__ __launch_bounds__(512, 1)
void conv_hmma_kernel(const float* __restrict__ bn_gamma,
                      const float* __restrict__ bn_beta,
                      const float* __restrict__ bn_mean,
                      const float* __restrict__ bn_var,
                      float* __restrict__ out) {
    const int tid  = threadIdx.x;
    const int lane = tid & 31;
    const int wid  = tid >> 5;
    const int wm   = wid & 3;          // warp row (0..3) -> 64 oc
    const int wn   = wid >> 2;         // warp col (0..3) -> 32 px
    const int p0   = blockIdx.x * 128;
    const int b    = blockIdx.y;

    const uint32_t sb = smem_u32(smem_raw);
    const uint32_t bw = sb + BWIN_OFF;

    // ---- B window staging: rows p0-59 .. p0+196 (256 rows x 512B) ----
    // store 16B chunk c of row r at column (c ^ (r&7))
    {
        const __half* gp = g_pimg + ((size_t)b * PTOT + PPAD + p0 - 59) * CIN;
        #pragma unroll
        for (int i = 0; i < 16; i++) {
            int idx = i * 512 + tid;
            int r = idx >> 5, c = idx & 31;
            cp16(bw + r * 512 + (((uint32_t)(c ^ (r & 7))) << 4),
                 gp + (size_t)r * CIN + c * 8);
        }
        CP_COMMIT();
    }

    // ---- A staging: 256 rows x 64 ci (128B rows, SW128 swizzle) ----
    const int srow = tid >> 1;               // 0..255
    const int scol = (tid & 1) * 4;          // 16B seg base 0 or 4
    const __half* cwrow = g_cw + (size_t)(b * COUT + srow) * KTOT;

    auto stageA = [&](int it, uint32_t stb) {
        const __half* ga = cwrow + it * 64 + scol * 8;
        uint32_t so = srow * 128 + scol * 16;
        #pragma unroll
        for (int i = 0; i < 4; i++)
            cp16(stb + SWZ(so + i * 16), ga + i * 8);
        CP_COMMIT();
    };

    float d[4][4][4];
    #pragma unroll
    for (int im = 0; im < 4; im++)
        #pragma unroll
        for (int in = 0; in < 4; in++)
            #pragma unroll
            for (int e = 0; e < 4; e++) d[im][in][e] = 0.f;

    // per-lane ldmatrix address pieces
    const int a_row = lane & 15;
    const int a_kh  = (lane >> 4) * 8;
    const int b_mi  = lane >> 3;                         // matrix 0..3
    const int b_row = ((b_mi >> 1) << 3) + (lane & 7);   // n within 16
    const int b_ck  = b_mi & 1;                          // k-half chunk

    stageA(0, sb);

    for (int it = 0; it < NCH; it++) {
        CP_WAIT0();                    // retire A(it) (+Bwin at it=0)
        __syncthreads();               // also separates reads of buf (it+1)&1
        if (it + 1 < NCH) stageA(it + 1, sb + ((it + 1) & 1) * ASTG);

        uint32_t as = sb + (it & 1) * ASTG;
        const int kpos = it >> 2;
        const int cchunk = (it & 3) * 8;     // 16B-chunk base of ci block
        const int woff = 59 + (kpos / 3) * PROW + (kpos % 3) - (PROW + 1);

        #pragma unroll
        for (int kk = 0; kk < 4; kk++) {
            uint32_t a[4][4];
            #pragma unroll
            for (int im = 0; im < 4; im++) {
                uint32_t byte = (wm * 64 + im * 16 + a_row) * 128 +
                                (kk * 16 + a_kh) * 2;
                ldmx4(a[im], as + SWZ(byte));
            }
            uint32_t bf[2][4];
            #pragma unroll
            for (int j = 0; j < 2; j++) {
                int wrow = woff + wn * 32 + j * 16 + b_row;
                int ck   = cchunk + kk * 2 + b_ck;
                ldmx4(bf[j], bw + wrow * 512 +
                             (((uint32_t)(ck ^ (wrow & 7))) << 4));
            }
            #pragma unroll
            for (int im = 0; im < 4; im++)
                #pragma unroll
                for (int in = 0; in < 4; in++)
                    mma16816(d[im][in], a[im],
                             bf[in >> 1][(in & 1) * 2],
                             bf[in >> 1][(in & 1) * 2 + 1]);
        }
    }

    // ---- epilogue: BN + SiLU + masked store ----
    const int t4 = lane >> 2, tp = lane & 3;
    #pragma unroll
    for (int im = 0; im < 4; im++) {
        int mloc = wm * 64 + im * 16 + t4;
        #pragma unroll
        for (int h = 0; h < 2; h++) {
            int oc = mloc + h * 8;
            float inv = bn_gamma[oc] * rsqrtf(bn_var[oc] + 1e-5f);
            float bia = bn_beta[oc] - bn_mean[oc] * inv;
            float* ob = out + (size_t)(b * COUT + oc) * HWSZ;
            #pragma unroll
            for (int in = 0; in < 4; in++) {
                int pbase = p0 + wn * 32 + in * 8 + tp * 2;
                #pragma unroll
                for (int e = 0; e < 2; e++) {
                    int p = pbase + e;
                    int rr = p / PROW - 1, ww = p % PROW - 1;
                    if (rr >= 0 && rr < HH && ww >= 0 && ww < WW) {
                        float z = d[im][in][h * 2 + e] * inv + bia;
                        ob[rr * WW + ww] = z / (1.f + __expf(-z));
                    }
                }
            }
        }
    }
}

// ---------------------------------------------------------------------------
extern "C" void kernel_launch(void* const* d_in, const int* in_sizes, int n_in,
                              void* d_out, int out_size) {
    const float* x         = (const float*)d_in[0];
    const float* routing_w = (const float*)d_in[1];
    const float* routing_b = (const float*)d_in[2];
    const float* kernel_w  = (const float*)d_in[3];
    const float* bn_gamma  = (const float*)d_in[4];
    const float* bn_beta   = (const float*)d_in[5];
    const float* bn_mean   = (const float*)d_in[6];
    const float* bn_var    = (const float*)d_in[7];
    float* out = (float*)d_out;

    cudaFuncSetAttribute(conv_hmma_kernel,
                         cudaFuncAttributeMaxDynamicSharedMemorySize, SMEM_DYN);

    pool_kernel<<<BATCH * CIN, 128>>>(x);
    route_kernel<<<1, 128>>>(routing_w, routing_b);
    combine_kernel<<<COUT, 256>>>(kernel_w);
    prep_kernel<<<dim3(PTOT / 64, CIN / 64, BATCH), 256>>>(x);

    dim3 grid(NT, BATCH);
    conv_hmma_kernel<<<grid, 512, SMEM_DYN>>>(bn_gamma, bn_beta, bn_mean,
                                              bn_var, out);
}